// round 14
// baseline (speedup 1.0000x reference)
#include <cuda_runtime.h>
#include <cuda_fp16.h>
#include <cstdint>

#define B_    8
#define R_    4
#define N_    1024
#define DIN_  256
#define DOUT_ 256

#define ADJ_SCALE 1024.0f
#define INV_SCALE (1.0f / 1024.0f)

// ---------------------------------------------------------------------------
// Global scratch (device globals; allocation in kernel_launch is forbidden)
// ---------------------------------------------------------------------------
__device__ __half g_text_hi[(size_t)B_ * N_ * DIN_];
__device__ __half g_text_lo[(size_t)B_ * N_ * DIN_];
__device__ __half g_W[(size_t)R_ * DIN_ * DOUT_];
__device__ __half g_Z[(size_t)B_ * R_ * N_ * DOUT_];     // Z[b,r][j][d] fp16
__device__ __half g_adj[(size_t)B_ * R_ * N_ * N_];      // rinv*1024-scaled adj (fp16)
#define PART_HALF ((size_t)B_ * N_ * DOUT_)              // 2,097,152 floats
__device__ float  g_part[2 * PART_HALF];                 // K-split partials (16 MB)

// ---------------------------------------------------------------------------
// PTX helpers (compute_103-safe: mma.sync / ldmatrix / cp.async)
// ---------------------------------------------------------------------------
__device__ __forceinline__ uint32_t smem_u32(const void* p) {
    uint32_t a;
    asm("{ .reg .u64 t; cvta.to.shared.u64 t, %1; cvt.u32.u64 %0, t; }" : "=r"(a) : "l"(p));
    return a;
}
__device__ __forceinline__ void ldsm_x4(uint32_t addr, uint32_t& r0, uint32_t& r1,
                                        uint32_t& r2, uint32_t& r3) {
    asm volatile("ldmatrix.sync.aligned.m8n8.x4.shared.b16 {%0,%1,%2,%3}, [%4];"
                 : "=r"(r0), "=r"(r1), "=r"(r2), "=r"(r3) : "r"(addr));
}
__device__ __forceinline__ void ldsm_x4_t(uint32_t addr, uint32_t& r0, uint32_t& r1,
                                          uint32_t& r2, uint32_t& r3) {
    asm volatile("ldmatrix.sync.aligned.m8n8.x4.trans.shared.b16 {%0,%1,%2,%3}, [%4];"
                 : "=r"(r0), "=r"(r1), "=r"(r2), "=r"(r3) : "r"(addr));
}
__device__ __forceinline__ void mma_f16(float* c, const uint32_t a[4], uint32_t b0, uint32_t b1) {
    asm volatile("mma.sync.aligned.m16n8k16.row.col.f32.f16.f16.f32 "
                 "{%0,%1,%2,%3}, {%4,%5,%6,%7}, {%8,%9}, {%0,%1,%2,%3};"
                 : "+f"(c[0]), "+f"(c[1]), "+f"(c[2]), "+f"(c[3])
                 : "r"(a[0]), "r"(a[1]), "r"(a[2]), "r"(a[3]), "r"(b0), "r"(b1));
}
#define CP_ASYNC16(dst, src) \
    asm volatile("cp.async.cg.shared.global [%0], [%1], 16;" :: "r"(dst), "l"(src) : "memory")
#define CP_COMMIT()  asm volatile("cp.async.commit_group;" ::: "memory")
#define CP_WAIT0()   asm volatile("cp.async.wait_group 0;" ::: "memory")
#define CP_WAIT1()   asm volatile("cp.async.wait_group 1;" ::: "memory")

__device__ __forceinline__ void split_h2(float x, float y, uint32_t& hw, uint32_t& lw) {
    __half hx = __float2half_rn(x), hy = __float2half_rn(y);
    hw = ((uint32_t)__half_as_ushort(hy) << 16) | __half_as_ushort(hx);
    __half lx = __float2half_rn(x - __half2float(hx));
    __half ly = __float2half_rn(y - __half2float(hy));
    lw = ((uint32_t)__half_as_ushort(ly) << 16) | __half_as_ushort(lx);
}
__device__ __forceinline__ uint32_t pack_h2(float x, float y) {
    __half hx = __float2half_rn(x), hy = __float2half_rn(y);
    return ((uint32_t)__half_as_ushort(hy) << 16) | __half_as_ushort(hx);
}

// ---------------------------------------------------------------------------
// smem layouts, padded strides — conflict-free ldmatrix
//   A tile: 128 rows x 64 fp16 (128B) stride 144 -> 18432 B
//   B tile:  64 rows x 128 fp16 (256B) stride 272 -> 17408 B
// ---------------------------------------------------------------------------
#define A_STRIDE  144
#define B_STRIDE  272
// stage 1 buffer: A hi + A lo + B
#define S1_OFF_AHI 0
#define S1_OFF_ALO 18432
#define S1_OFF_B   36864
#define S1_BUF     54272
#define SMEM1_TOTAL (2 * S1_BUF)       // 108544
// stage 2 buffer: A (single) + B ; 3-stage pipeline, 2 CTAs/SM
#define S2_OFF_A   0
#define S2_OFF_B   18432
#define S2_BUF     35840
#define S2_STAGES  3
#define SMEM2_TOTAL (S2_STAGES * S2_BUF)   // 107520 -> 2 CTAs/SM

// 8 warps: warp (wm, wn) = (warp&3, warp>>2) computes 32x64 of the 128x128 tile.

// Stage-1 chunk: 2-pass (a_hi*b + a_lo*b)
__device__ __forceinline__ void compute_chunk_2p(uint32_t sb_buf, int wm, int wn, int g, int lr,
                                                 float (&acc)[2][8][4]) {
#pragma unroll
    for (int ks = 0; ks < 4; ++ks) {
        const int k0 = ks * 16;
        uint32_t ah[2][4], al[2][4];
#pragma unroll
        for (int mf = 0; mf < 2; ++mf) {
            uint32_t row  = wm * 32 + mf * 16 + (g & 1) * 8 + lr;
            uint32_t colb = (uint32_t)((g >> 1) * 16 + k0 * 2);
            ldsm_x4(sb_buf + S1_OFF_AHI + row * A_STRIDE + colb,
                    ah[mf][0], ah[mf][1], ah[mf][2], ah[mf][3]);
            ldsm_x4(sb_buf + S1_OFF_ALO + row * A_STRIDE + colb,
                    al[mf][0], al[mf][1], al[mf][2], al[mf][3]);
        }
        uint32_t bb[8][2];
#pragma unroll
        for (int nb = 0; nb < 4; ++nb) {
            uint32_t krow = (uint32_t)(k0 + (g & 1) * 8 + lr);
            uint32_t colb = (uint32_t)((wn * 64 + nb * 16 + (g >> 1) * 8) * 2);
            uint32_t q0, q1, q2, q3;
            ldsm_x4_t(sb_buf + S1_OFF_B + krow * B_STRIDE + colb, q0, q1, q2, q3);
            bb[nb * 2][0] = q0; bb[nb * 2][1] = q1;
            bb[nb * 2 + 1][0] = q2; bb[nb * 2 + 1][1] = q3;
        }
#pragma unroll
        for (int mf = 0; mf < 2; ++mf)
#pragma unroll
            for (int nf = 0; nf < 8; ++nf)
                mma_f16(acc[mf][nf], ah[mf], bb[nf][0], bb[nf][1]);
#pragma unroll
        for (int mf = 0; mf < 2; ++mf)
#pragma unroll
            for (int nf = 0; nf < 8; ++nf)
                mma_f16(acc[mf][nf], al[mf], bb[nf][0], bb[nf][1]);
    }
}

// Stage-2 chunk: single pass (adj single fp16), warp tile 32x64 (proven).
__device__ __forceinline__ void compute_chunk_1p(uint32_t sb_buf, int wm, int wn, int g, int lr,
                                                 float (&acc)[2][8][4]) {
#pragma unroll
    for (int ks = 0; ks < 4; ++ks) {
        const int k0 = ks * 16;
        uint32_t aa[2][4];
#pragma unroll
        for (int mf = 0; mf < 2; ++mf) {
            uint32_t row  = wm * 32 + mf * 16 + (g & 1) * 8 + lr;
            uint32_t colb = (uint32_t)((g >> 1) * 16 + k0 * 2);
            ldsm_x4(sb_buf + S2_OFF_A + row * A_STRIDE + colb,
                    aa[mf][0], aa[mf][1], aa[mf][2], aa[mf][3]);
        }
        uint32_t bb[8][2];
#pragma unroll
        for (int nb = 0; nb < 4; ++nb) {
            uint32_t krow = (uint32_t)(k0 + (g & 1) * 8 + lr);
            uint32_t colb = (uint32_t)((wn * 64 + nb * 16 + (g >> 1) * 8) * 2);
            uint32_t q0, q1, q2, q3;
            ldsm_x4_t(sb_buf + S2_OFF_B + krow * B_STRIDE + colb, q0, q1, q2, q3);
            bb[nb * 2][0] = q0; bb[nb * 2][1] = q1;
            bb[nb * 2 + 1][0] = q2; bb[nb * 2 + 1][1] = q3;
        }
#pragma unroll
        for (int mf = 0; mf < 2; ++mf)
#pragma unroll
            for (int nf = 0; nf < 8; ++nf)
                mma_f16(acc[mf][nf], aa[mf], bb[nf][0], bb[nf][1]);
    }
}

// ---------------------------------------------------------------------------
// conv_inputs: text -> fp16 hi/lo ; W -> fp16 single.
// ---------------------------------------------------------------------------
__global__ __launch_bounds__(256) void conv_inputs(const float* __restrict__ text,
                                                   const float* __restrict__ weight) {
    const size_t NT4 = (size_t)B_ * N_ * DIN_ / 4;            // 524288 float4s
    size_t i = (size_t)blockIdx.x * 256 + threadIdx.x;        // total 589824
    if (i < NT4) {
        float4 v = reinterpret_cast<const float4*>(text)[i];
        uint32_t h0, l0, h1, l1;
        split_h2(v.x, v.y, h0, l0);
        split_h2(v.z, v.w, h1, l1);
        *reinterpret_cast<uint2*>(g_text_hi + i * 4) = make_uint2(h0, h1);
        *reinterpret_cast<uint2*>(g_text_lo + i * 4) = make_uint2(l0, l1);
    } else {
        size_t j = i - NT4;
        float4 v = reinterpret_cast<const float4*>(weight)[j];
        *reinterpret_cast<uint2*>(g_W + j * 4) =
            make_uint2(pack_h2(v.x, v.y), pack_h2(v.z, v.w));
    }
}

// ---------------------------------------------------------------------------
// adj_convert: one warp per row. rowsum -> rinv; write (adj * rinv * 1024) as
// single fp16. Standalone (fusing with smem-heavy launches regresses; R11).
// ---------------------------------------------------------------------------
__global__ __launch_bounds__(256) void adj_convert(const float* __restrict__ adj) {
    const int warp = threadIdx.x >> 5, lane = threadIdx.x & 31;
    const int row  = blockIdx.x * 8 + warp;                    // 0 .. 32767
    const float* p = adj + (size_t)row * N_;

    float4 v[8];
    float s = 0.f;
#pragma unroll
    for (int t = 0; t < 8; ++t) {
        v[t] = *reinterpret_cast<const float4*>(p + t * 128 + lane * 4);
        s += (v[t].x + v[t].y) + (v[t].z + v[t].w);
    }
#pragma unroll
    for (int o = 16; o > 0; o >>= 1) s += __shfl_xor_sync(0xffffffffu, s, o);
    const float rinv = (s == 0.f) ? 0.f : ADJ_SCALE / s;

    __half* hp = g_adj + (size_t)row * N_;
#pragma unroll
    for (int t = 0; t < 8; ++t) {
        *reinterpret_cast<uint2*>(hp + t * 128 + lane * 4) =
            make_uint2(pack_h2(v[t].x * rinv, v[t].y * rinv),
                       pack_h2(v[t].z * rinv, v[t].w * rinv));
    }
}

// ---------------------------------------------------------------------------
// Stage 1: Z[b,r] = text[b] @ W[r]  (fp16 2-pass HMMA); writes Z fp16.
// ---------------------------------------------------------------------------
__global__ __launch_bounds__(256, 1) void rgc_stage1() {
    extern __shared__ char smem[];
    const uint32_t sb = smem_u32(smem);
    const int tid = threadIdx.x, lane = tid & 31, warp = tid >> 5;
    const int wm = warp & 3, wn = warp >> 2;
    const int g = lane >> 3, lr = lane & 7;

    const int bz = blockIdx.z;            // b*R + r
    const int b  = bz >> 2, r = bz & 3;
    const int tile_m = blockIdx.y * 128;  // j
    const int tile_n = blockIdx.x * 128;  // d

    float acc[2][8][4];
#pragma unroll
    for (int mf = 0; mf < 2; ++mf)
#pragma unroll
        for (int nf = 0; nf < 8; ++nf)
#pragma unroll
            for (int q = 0; q < 4; ++q) acc[mf][nf][q] = 0.f;

    auto issue = [&](int kc) {
        const uint32_t bufb = (uint32_t)(kc & 1) * S1_BUF;
        const __half* th = g_text_hi + ((size_t)b * N_ + tile_m) * DIN_ + kc * 64;
        const __half* tl = g_text_lo + ((size_t)b * N_ + tile_m) * DIN_ + kc * 64;
#pragma unroll
        for (int i = 0; i < 4; ++i) {
            int idx = i * 256 + tid;
            int row = idx >> 3, k8 = idx & 7;
            uint32_t d = bufb + row * A_STRIDE + k8 * 16;
            CP_ASYNC16(sb + d + S1_OFF_AHI, th + (size_t)row * DIN_ + k8 * 8);
            CP_ASYNC16(sb + d + S1_OFF_ALO, tl + (size_t)row * DIN_ + k8 * 8);
        }
        const __half* wp = g_W + ((size_t)r * DIN_ + kc * 64) * DOUT_ + tile_n;
#pragma unroll
        for (int i = 0; i < 4; ++i) {
            int idx = i * 256 + tid;
            int k = idx >> 4, n16 = idx & 15;
            CP_ASYNC16(sb + bufb + k * B_STRIDE + n16 * 16 + S1_OFF_B,
                       wp + (size_t)k * DOUT_ + n16 * 8);
        }
        CP_COMMIT();
    };

    issue(0);
    CP_WAIT0();
    __syncthreads();

    for (int c = 0; c < 4; ++c) {
        if (c + 1 < 4) issue(c + 1);
        compute_chunk_2p(sb + (uint32_t)(c & 1) * S1_BUF, wm, wn, g, lr, acc);
        CP_WAIT0();
        __syncthreads();
    }

    // Epilogue: Z (single fp16)
#pragma unroll
    for (int mf = 0; mf < 2; ++mf)
#pragma unroll
        for (int nf = 0; nf < 8; ++nf) {
            int row0 = tile_m + wm * 32 + mf * 16 + (lane >> 2);
            int col  = tile_n + wn * 64 + nf * 8 + (lane & 3) * 2;
            size_t off0 = ((size_t)bz * N_ + row0) * DOUT_ + col;
            *reinterpret_cast<uint32_t*>(&g_Z[off0]) = pack_h2(acc[mf][nf][0], acc[mf][nf][1]);
            size_t off1 = off0 + (size_t)8 * DOUT_;
            *reinterpret_cast<uint32_t*>(&g_Z[off1]) = pack_h2(acc[mf][nf][2], acc[mf][nf][3]);
        }
}

// ---------------------------------------------------------------------------
// Stage 2 (K-split x2): g_part[half] = partial over relations {2*half, 2*half+1}
// (half 0 also folds in bias). Grid 256 CTAs -> SMs genuinely hold 2 CTAs:
// 4 warps/SMSP in two independent barrier domains, warp tile 32x64 unchanged.
// ---------------------------------------------------------------------------
__global__ __launch_bounds__(256, 2) void rgc_stage2(const float* __restrict__ bias) {
    extern __shared__ char smem[];
    const uint32_t sb = smem_u32(smem);
    const int tid = threadIdx.x, lane = tid & 31, warp = tid >> 5;
    const int wm = warp & 3, wn = warp >> 2;
    const int g = lane >> 3, lr = lane & 7;

    const int half   = blockIdx.x >> 1;
    const int b      = blockIdx.z;
    const int tile_m = blockIdx.y * 128;           // i
    const int tile_n = (blockIdx.x & 1) * 128;     // d

    float acc[2][8][4];
#pragma unroll
    for (int mf = 0; mf < 2; ++mf)
#pragma unroll
        for (int nf = 0; nf < 8; ++nf)
#pragma unroll
            for (int q = 0; q < 4; ++q) acc[mf][nf][q] = 0.f;

    // chunk c in [half*32, half*32+32): r = c>>4, kc = c&15
    auto issue = [&](int c) {
        const int r = c >> 4, kc = c & 15;
        const uint32_t bufb = (uint32_t)(c % S2_STAGES) * S2_BUF;
        const __half* ap = g_adj + (((size_t)(b * R_ + r)) * N_ + tile_m) * N_ + kc * 64;
#pragma unroll
        for (int i = 0; i < 4; ++i) {
            int idx = i * 256 + tid;
            int row = idx >> 3, k8 = idx & 7;
            CP_ASYNC16(sb + bufb + row * A_STRIDE + k8 * 16 + S2_OFF_A,
                       ap + (size_t)row * N_ + k8 * 8);
        }
        const __half* zp = g_Z + (((size_t)(b * R_ + r)) * N_ + kc * 64) * DOUT_ + tile_n;
#pragma unroll
        for (int i = 0; i < 4; ++i) {
            int idx = i * 256 + tid;
            int k = idx >> 4, n16 = idx & 15;
            CP_ASYNC16(sb + bufb + k * B_STRIDE + n16 * 16 + S2_OFF_B,
                       zp + (size_t)k * DOUT_ + n16 * 8);
        }
        CP_COMMIT();
    };

    const int c0 = half * 32, c1 = c0 + 32;
    issue(c0); issue(c0 + 1);

    for (int c = c0; c < c1; ++c) {
        CP_WAIT1();                      // chunk c landed (1 younger may be in flight)
        __syncthreads();                 // all warps past compute(c-1); its buffer free
        if (c + 2 < c1) issue(c + 2); else CP_COMMIT();   // uniform group accounting
        compute_chunk_1p(sb + (uint32_t)(c % S2_STAGES) * S2_BUF, wm, wn, g, lr, acc);
    }

    // Epilogue: undo ADJ_SCALE; half 0 folds in bias; store partial fp32
    float* po = g_part + (size_t)half * PART_HALF + ((size_t)b * N_) * DOUT_;
#pragma unroll
    for (int mf = 0; mf < 2; ++mf)
#pragma unroll
        for (int nf = 0; nf < 8; ++nf) {
            int row0 = tile_m + wm * 32 + mf * 16 + (lane >> 2);
            int col  = tile_n + wn * 64 + nf * 8 + (lane & 3) * 2;
            float b0 = (half == 0) ? bias[col] : 0.f;
            float b1 = (half == 0) ? bias[col + 1] : 0.f;
            float* o0 = po + (size_t)row0 * DOUT_ + col;
            *reinterpret_cast<float2*>(o0) =
                make_float2(acc[mf][nf][0] * INV_SCALE + b0, acc[mf][nf][1] * INV_SCALE + b1);
            float* o1 = o0 + (size_t)8 * DOUT_;
            *reinterpret_cast<float2*>(o1) =
                make_float2(acc[mf][nf][2] * INV_SCALE + b0, acc[mf][nf][3] * INV_SCALE + b1);
        }
}

// ---------------------------------------------------------------------------
// reduce_out: out = part0 + part1 (float4 streaming, 24 MB traffic).
// ---------------------------------------------------------------------------
__global__ __launch_bounds__(256) void reduce_out(float* __restrict__ out) {
    size_t i = ((size_t)blockIdx.x * 256 + threadIdx.x);      // float4 index, 524288 total
    float4 a = reinterpret_cast<const float4*>(g_part)[i];
    float4 c = reinterpret_cast<const float4*>(g_part + PART_HALF)[i];
    reinterpret_cast<float4*>(out)[i] =
        make_float4(a.x + c.x, a.y + c.y, a.z + c.z, a.w + c.w);
}

// ---------------------------------------------------------------------------
extern "C" void kernel_launch(void* const* d_in, const int* in_sizes, int n_in,
                              void* d_out, int out_size) {
    const float* text   = (const float*)d_in[0];  // [8,1024,256]
    const float* adj    = (const float*)d_in[1];  // [8,4,1024,1024]
    const float* weight = (const float*)d_in[2];  // [4,256,256]
    const float* bias   = (const float*)d_in[3];  // [256]
    float* out = (float*)d_out;                   // [8,1024,256]

    cudaFuncSetAttribute(rgc_stage1, cudaFuncAttributeMaxDynamicSharedMemorySize, SMEM1_TOTAL);
    cudaFuncSetAttribute(rgc_stage2, cudaFuncAttributeMaxDynamicSharedMemorySize, SMEM2_TOTAL);

    // 1) text -> fp16 hi/lo, W -> fp16
    conv_inputs<<<2304, 256>>>(text, weight);
    // 2) adj -> single fp16, row-normalized (rowsum fused)
    adj_convert<<<(B_ * R_ * N_) / 8, 256>>>(adj);
    // 3) Z = text @ W (fp16 2-pass HMMA)
    rgc_stage1<<<dim3(DOUT_ / 128, N_ / 128, B_ * R_), 256, SMEM1_TOTAL>>>();
    // 4) partials over relation halves (grid 256 -> true 2 CTAs/SM)
    rgc_stage2<<<dim3(2 * (DOUT_ / 128), N_ / 128, B_), 256, SMEM2_TOTAL>>>(bias);
    // 5) out = part0 + part1
    reduce_out<<<(B_ * N_ * DOUT_) / 4 / 256, 256>>>(out);
}

// round 15
// speedup vs baseline: 1.0378x; 1.0378x over previous
#include <cuda_runtime.h>
#include <cuda_fp16.h>
#include <cstdint>

#define B_    8
#define R_    4
#define N_    1024
#define DIN_  256
#define DOUT_ 256

#define ADJ_SCALE 1024.0f
#define INV_SCALE (1.0f / 1024.0f)

// ---------------------------------------------------------------------------
// Global scratch (device globals; allocation in kernel_launch is forbidden)
// ---------------------------------------------------------------------------
__device__ __half g_text[(size_t)B_ * N_ * DIN_];
__device__ __half g_W[(size_t)R_ * DIN_ * DOUT_];
__device__ __half g_Z[(size_t)B_ * R_ * N_ * DOUT_];     // Z[b,r][j][d] fp16
__device__ __half g_adj[(size_t)B_ * R_ * N_ * N_];      // rinv*1024-scaled adj (fp16)
#define PART_SZ ((size_t)B_ * N_ * DOUT_)                // 2,097,152 floats
__device__ float  g_part[R_ * PART_SZ];                  // per-relation partials (33.5 MB)

// ---------------------------------------------------------------------------
// PTX helpers (compute_103-safe: mma.sync / ldmatrix / cp.async)
// ---------------------------------------------------------------------------
__device__ __forceinline__ uint32_t smem_u32(const void* p) {
    uint32_t a;
    asm("{ .reg .u64 t; cvta.to.shared.u64 t, %1; cvt.u32.u64 %0, t; }" : "=r"(a) : "l"(p));
    return a;
}
__device__ __forceinline__ void ldsm_x4(uint32_t addr, uint32_t& r0, uint32_t& r1,
                                        uint32_t& r2, uint32_t& r3) {
    asm volatile("ldmatrix.sync.aligned.m8n8.x4.shared.b16 {%0,%1,%2,%3}, [%4];"
                 : "=r"(r0), "=r"(r1), "=r"(r2), "=r"(r3) : "r"(addr));
}
__device__ __forceinline__ void ldsm_x4_t(uint32_t addr, uint32_t& r0, uint32_t& r1,
                                          uint32_t& r2, uint32_t& r3) {
    asm volatile("ldmatrix.sync.aligned.m8n8.x4.trans.shared.b16 {%0,%1,%2,%3}, [%4];"
                 : "=r"(r0), "=r"(r1), "=r"(r2), "=r"(r3) : "r"(addr));
}
__device__ __forceinline__ void mma_f16(float* c, const uint32_t a[4], uint32_t b0, uint32_t b1) {
    asm volatile("mma.sync.aligned.m16n8k16.row.col.f32.f16.f16.f32 "
                 "{%0,%1,%2,%3}, {%4,%5,%6,%7}, {%8,%9}, {%0,%1,%2,%3};"
                 : "+f"(c[0]), "+f"(c[1]), "+f"(c[2]), "+f"(c[3])
                 : "r"(a[0]), "r"(a[1]), "r"(a[2]), "r"(a[3]), "r"(b0), "r"(b1));
}
#define CP_ASYNC16(dst, src) \
    asm volatile("cp.async.cg.shared.global [%0], [%1], 16;" :: "r"(dst), "l"(src) : "memory")
#define CP_COMMIT()  asm volatile("cp.async.commit_group;" ::: "memory")
#define CP_WAIT0()   asm volatile("cp.async.wait_group 0;" ::: "memory")
#define CP_WAIT1()   asm volatile("cp.async.wait_group 1;" ::: "memory")

__device__ __forceinline__ uint32_t pack_h2(float x, float y) {
    __half hx = __float2half_rn(x), hy = __float2half_rn(y);
    return ((uint32_t)__half_as_ushort(hy) << 16) | __half_as_ushort(hx);
}

// ---------------------------------------------------------------------------
// smem layouts, padded strides — conflict-free ldmatrix
//   A-row: 64 fp16 = 128B, stride 144. B tile: 64 rows x 128 fp16, stride 272.
// ---------------------------------------------------------------------------
#define A_STRIDE  144
#define B_STRIDE  272
// stage 1 buffer: A (128 rows) + B
#define S1_OFF_A   0
#define S1_OFF_B   18432
#define S1_BUF     35840
#define SMEM1_TOTAL (2 * S1_BUF)           // 71680
// stage 2 buffer: A (256 rows) + B
#define S2_OFF_A   0
#define S2_OFF_B   36864                   // 256 * 144
#define S2_BUF     54272                   // 36864 + 17408
#define S2_STAGES  3
#define SMEM2_TOTAL (S2_STAGES * S2_BUF)   // 162816

// ---------------------------------------------------------------------------
// Stage-1 chunk (128x128 CTA tile, 8 warps, warp tile 32x64, single pass).
// ---------------------------------------------------------------------------
__device__ __forceinline__ void compute_chunk_s1(uint32_t sb_buf, int wm, int wn, int g, int lr,
                                                 float (&acc)[2][8][4]) {
#pragma unroll
    for (int ks = 0; ks < 4; ++ks) {
        const int k0 = ks * 16;
        uint32_t aa[2][4];
#pragma unroll
        for (int mf = 0; mf < 2; ++mf) {
            uint32_t row  = wm * 32 + mf * 16 + (g & 1) * 8 + lr;
            uint32_t colb = (uint32_t)((g >> 1) * 16 + k0 * 2);
            ldsm_x4(sb_buf + S1_OFF_A + row * A_STRIDE + colb,
                    aa[mf][0], aa[mf][1], aa[mf][2], aa[mf][3]);
        }
        uint32_t bb[8][2];
#pragma unroll
        for (int nb = 0; nb < 4; ++nb) {
            uint32_t krow = (uint32_t)(k0 + (g & 1) * 8 + lr);
            uint32_t colb = (uint32_t)((wn * 64 + nb * 16 + (g >> 1) * 8) * 2);
            uint32_t q0, q1, q2, q3;
            ldsm_x4_t(sb_buf + S1_OFF_B + krow * B_STRIDE + colb, q0, q1, q2, q3);
            bb[nb * 2][0] = q0; bb[nb * 2][1] = q1;
            bb[nb * 2 + 1][0] = q2; bb[nb * 2 + 1][1] = q3;
        }
#pragma unroll
        for (int mf = 0; mf < 2; ++mf)
#pragma unroll
            for (int nf = 0; nf < 8; ++nf)
                mma_f16(acc[mf][nf], aa[mf], bb[nf][0], bb[nf][1]);
    }
}

// ---------------------------------------------------------------------------
// Stage-2 chunk (256x128 CTA tile, 8 warps, warp tile 64x64):
// 8 ldsm -> 32 MMA per ks-step (ratio 4.0).
// wm = warp & 3 (4 x 64 rows), wn = warp >> 2 (2 x 64 cols).
// ---------------------------------------------------------------------------
__device__ __forceinline__ void compute_chunk_s2(uint32_t sb_buf, int wm, int wn, int g, int lr,
                                                 float (&acc)[4][8][4]) {
#pragma unroll
    for (int ks = 0; ks < 4; ++ks) {
        const int k0 = ks * 16;
        uint32_t aa[4][4];
#pragma unroll
        for (int mf = 0; mf < 4; ++mf) {
            uint32_t row  = wm * 64 + mf * 16 + (g & 1) * 8 + lr;
            uint32_t colb = (uint32_t)((g >> 1) * 16 + k0 * 2);
            ldsm_x4(sb_buf + S2_OFF_A + row * A_STRIDE + colb,
                    aa[mf][0], aa[mf][1], aa[mf][2], aa[mf][3]);
        }
        uint32_t bb[8][2];
#pragma unroll
        for (int nb = 0; nb < 4; ++nb) {
            uint32_t krow = (uint32_t)(k0 + (g & 1) * 8 + lr);
            uint32_t colb = (uint32_t)((wn * 64 + nb * 16 + (g >> 1) * 8) * 2);
            uint32_t q0, q1, q2, q3;
            ldsm_x4_t(sb_buf + S2_OFF_B + krow * B_STRIDE + colb, q0, q1, q2, q3);
            bb[nb * 2][0] = q0; bb[nb * 2][1] = q1;
            bb[nb * 2 + 1][0] = q2; bb[nb * 2 + 1][1] = q3;
        }
#pragma unroll
        for (int mf = 0; mf < 4; ++mf)
#pragma unroll
            for (int nf = 0; nf < 8; ++nf)
                mma_f16(acc[mf][nf], aa[mf], bb[nf][0], bb[nf][1]);
    }
}

// ---------------------------------------------------------------------------
// conv_inputs: text -> fp16 ; W -> fp16.
// ---------------------------------------------------------------------------
__global__ __launch_bounds__(256) void conv_inputs(const float* __restrict__ text,
                                                   const float* __restrict__ weight) {
    const size_t NT4 = (size_t)B_ * N_ * DIN_ / 4;            // 524288 float4s
    size_t i = (size_t)blockIdx.x * 256 + threadIdx.x;        // total 589824
    if (i < NT4) {
        float4 v = reinterpret_cast<const float4*>(text)[i];
        *reinterpret_cast<uint2*>(g_text + i * 4) =
            make_uint2(pack_h2(v.x, v.y), pack_h2(v.z, v.w));
    } else {
        size_t j = i - NT4;
        float4 v = reinterpret_cast<const float4*>(weight)[j];
        *reinterpret_cast<uint2*>(g_W + j * 4) =
            make_uint2(pack_h2(v.x, v.y), pack_h2(v.z, v.w));
    }
}

// ---------------------------------------------------------------------------
// adj_convert: one warp per row. rowsum -> rinv; write (adj * rinv * 1024) as
// fp16. Standalone (fusing with smem-heavy launches regresses; R11).
// ---------------------------------------------------------------------------
__global__ __launch_bounds__(256) void adj_convert(const float* __restrict__ adj) {
    const int warp = threadIdx.x >> 5, lane = threadIdx.x & 31;
    const int row  = blockIdx.x * 8 + warp;                    // 0 .. 32767
    const float* p = adj + (size_t)row * N_;

    float4 v[8];
    float s = 0.f;
#pragma unroll
    for (int t = 0; t < 8; ++t) {
        v[t] = *reinterpret_cast<const float4*>(p + t * 128 + lane * 4);
        s += (v[t].x + v[t].y) + (v[t].z + v[t].w);
    }
#pragma unroll
    for (int o = 16; o > 0; o >>= 1) s += __shfl_xor_sync(0xffffffffu, s, o);
    const float rinv = (s == 0.f) ? 0.f : ADJ_SCALE / s;

    __half* hp = g_adj + (size_t)row * N_;
#pragma unroll
    for (int t = 0; t < 8; ++t) {
        *reinterpret_cast<uint2*>(hp + t * 128 + lane * 4) =
            make_uint2(pack_h2(v[t].x * rinv, v[t].y * rinv),
                       pack_h2(v[t].z * rinv, v[t].w * rinv));
    }
}

// ---------------------------------------------------------------------------
// Stage 1: Z[b,r] = text[b] @ W[r]  (fp16 1-pass HMMA); writes Z fp16.
// ---------------------------------------------------------------------------
__global__ __launch_bounds__(256, 1) void rgc_stage1() {
    extern __shared__ char smem[];
    const uint32_t sb = smem_u32(smem);
    const int tid = threadIdx.x, lane = tid & 31, warp = tid >> 5;
    const int wm = warp & 3, wn = warp >> 2;
    const int g = lane >> 3, lr = lane & 7;

    const int bz = blockIdx.z;            // b*R + r
    const int b  = bz >> 2, r = bz & 3;
    const int tile_m = blockIdx.y * 128;  // j
    const int tile_n = blockIdx.x * 128;  // d

    float acc[2][8][4];
#pragma unroll
    for (int mf = 0; mf < 2; ++mf)
#pragma unroll
        for (int nf = 0; nf < 8; ++nf)
#pragma unroll
            for (int q = 0; q < 4; ++q) acc[mf][nf][q] = 0.f;

    auto issue = [&](int kc) {
        const uint32_t bufb = (uint32_t)(kc & 1) * S1_BUF;
        const __half* tp = g_text + ((size_t)b * N_ + tile_m) * DIN_ + kc * 64;
#pragma unroll
        for (int i = 0; i < 4; ++i) {
            int idx = i * 256 + tid;
            int row = idx >> 3, k8 = idx & 7;
            CP_ASYNC16(sb + bufb + row * A_STRIDE + k8 * 16 + S1_OFF_A,
                       tp + (size_t)row * DIN_ + k8 * 8);
        }
        const __half* wp = g_W + ((size_t)r * DIN_ + kc * 64) * DOUT_ + tile_n;
#pragma unroll
        for (int i = 0; i < 4; ++i) {
            int idx = i * 256 + tid;
            int k = idx >> 4, n16 = idx & 15;
            CP_ASYNC16(sb + bufb + k * B_STRIDE + n16 * 16 + S1_OFF_B,
                       wp + (size_t)k * DOUT_ + n16 * 8);
        }
        CP_COMMIT();
    };

    issue(0);
    CP_WAIT0();
    __syncthreads();

    for (int c = 0; c < 4; ++c) {
        if (c + 1 < 4) issue(c + 1);
        compute_chunk_s1(sb + (uint32_t)(c & 1) * S1_BUF, wm, wn, g, lr, acc);
        CP_WAIT0();
        __syncthreads();
    }

    // Epilogue: Z fp16
#pragma unroll
    for (int mf = 0; mf < 2; ++mf)
#pragma unroll
        for (int nf = 0; nf < 8; ++nf) {
            int row0 = tile_m + wm * 32 + mf * 16 + (lane >> 2);
            int col  = tile_n + wn * 64 + nf * 8 + (lane & 3) * 2;
            size_t off0 = ((size_t)bz * N_ + row0) * DOUT_ + col;
            *reinterpret_cast<uint32_t*>(&g_Z[off0]) = pack_h2(acc[mf][nf][0], acc[mf][nf][1]);
            size_t off1 = off0 + (size_t)8 * DOUT_;
            *reinterpret_cast<uint32_t*>(&g_Z[off1]) = pack_h2(acc[mf][nf][2], acc[mf][nf][3]);
        }
}

// ---------------------------------------------------------------------------
// Stage 2 (K-split by relation): g_part[r] = diag(rinv) adj[b,r] @ Z[b,r]
// (r==0 also folds bias). 256x128 CTA tile, warp tile 64x64 (MMA:LDSM = 4.0),
// 3-stage cp.async pipeline. Grid 256 CTAs.
// ---------------------------------------------------------------------------
__global__ __launch_bounds__(256, 1) void rgc_stage2(const float* __restrict__ bias) {
    extern __shared__ char smem[];
    const uint32_t sb = smem_u32(smem);
    const int tid = threadIdx.x, lane = tid & 31, warp = tid >> 5;
    const int wm = warp & 3, wn = warp >> 2;
    const int g = lane >> 3, lr = lane & 7;

    const int r      = blockIdx.x >> 1;            // relation 0..3
    const int tile_n = (blockIdx.x & 1) * 128;     // d
    const int tile_m = blockIdx.y * 256;           // i
    const int b      = blockIdx.z;

    float acc[4][8][4];
#pragma unroll
    for (int mf = 0; mf < 4; ++mf)
#pragma unroll
        for (int nf = 0; nf < 8; ++nf)
#pragma unroll
            for (int q = 0; q < 4; ++q) acc[mf][nf][q] = 0.f;

    // chunk kc in [0,16): K=64 slice of this relation's 1024-wide K
    auto issue = [&](int kc) {
        const uint32_t bufb = (uint32_t)(kc % S2_STAGES) * S2_BUF;
        const __half* ap = g_adj + (((size_t)(b * R_ + r)) * N_ + tile_m) * N_ + kc * 64;
#pragma unroll
        for (int i = 0; i < 8; ++i) {                          // 256x64 fp16 = 2048 x 16B
            int idx = i * 256 + tid;
            int row = idx >> 3, k8 = idx & 7;
            CP_ASYNC16(sb + bufb + row * A_STRIDE + k8 * 16 + S2_OFF_A,
                       ap + (size_t)row * N_ + k8 * 8);
        }
        const __half* zp = g_Z + (((size_t)(b * R_ + r)) * N_ + kc * 64) * DOUT_ + tile_n;
#pragma unroll
        for (int i = 0; i < 4; ++i) {                          // 64x128 fp16 = 1024 x 16B
            int idx = i * 256 + tid;
            int k = idx >> 4, n16 = idx & 15;
            CP_ASYNC16(sb + bufb + k * B_STRIDE + n16 * 16 + S2_OFF_B,
                       zp + (size_t)k * DOUT_ + n16 * 8);
        }
        CP_COMMIT();
    };

    issue(0); issue(1);

    for (int c = 0; c < 16; ++c) {
        CP_WAIT1();                      // chunk c landed (1 younger may be in flight)
        __syncthreads();                 // all warps past compute(c-1); its buffer free
        if (c + 2 < 16) issue(c + 2); else CP_COMMIT();   // uniform group accounting
        compute_chunk_s2(sb + (uint32_t)(c % S2_STAGES) * S2_BUF, wm, wn, g, lr, acc);
    }

    // Epilogue: undo ADJ_SCALE; r==0 folds bias; store partial fp32
    float* po = g_part + (size_t)r * PART_SZ + ((size_t)b * N_) * DOUT_;
#pragma unroll
    for (int mf = 0; mf < 4; ++mf)
#pragma unroll
        for (int nf = 0; nf < 8; ++nf) {
            int row0 = tile_m + wm * 64 + mf * 16 + (lane >> 2);
            int col  = tile_n + wn * 64 + nf * 8 + (lane & 3) * 2;
            float b0 = (r == 0) ? bias[col] : 0.f;
            float b1 = (r == 0) ? bias[col + 1] : 0.f;
            float* o0 = po + (size_t)row0 * DOUT_ + col;
            *reinterpret_cast<float2*>(o0) =
                make_float2(acc[mf][nf][0] * INV_SCALE + b0, acc[mf][nf][1] * INV_SCALE + b1);
            float* o1 = o0 + (size_t)8 * DOUT_;
            *reinterpret_cast<float2*>(o1) =
                make_float2(acc[mf][nf][2] * INV_SCALE + b0, acc[mf][nf][3] * INV_SCALE + b1);
        }
}

// ---------------------------------------------------------------------------
// reduce_out: out = part0 + part1 + part2 + part3 (float4 streaming).
// ---------------------------------------------------------------------------
__global__ __launch_bounds__(256) void reduce_out(float* __restrict__ out) {
    size_t i = ((size_t)blockIdx.x * 256 + threadIdx.x);      // float4 index, 524288 total
    float4 a = reinterpret_cast<const float4*>(g_part)[i];
    float4 c = reinterpret_cast<const float4*>(g_part + PART_SZ)[i];
    float4 d = reinterpret_cast<const float4*>(g_part + 2 * PART_SZ)[i];
    float4 e = reinterpret_cast<const float4*>(g_part + 3 * PART_SZ)[i];
    reinterpret_cast<float4*>(out)[i] =
        make_float4((a.x + c.x) + (d.x + e.x), (a.y + c.y) + (d.y + e.y),
                    (a.z + c.z) + (d.z + e.z), (a.w + c.w) + (d.w + e.w));
}

// ---------------------------------------------------------------------------
extern "C" void kernel_launch(void* const* d_in, const int* in_sizes, int n_in,
                              void* d_out, int out_size) {
    const float* text   = (const float*)d_in[0];  // [8,1024,256]
    const float* adj    = (const float*)d_in[1];  // [8,4,1024,1024]
    const float* weight = (const float*)d_in[2];  // [4,256,256]
    const float* bias   = (const float*)d_in[3];  // [256]
    float* out = (float*)d_out;                   // [8,1024,256]

    cudaFuncSetAttribute(rgc_stage1, cudaFuncAttributeMaxDynamicSharedMemorySize, SMEM1_TOTAL);
    cudaFuncSetAttribute(rgc_stage2, cudaFuncAttributeMaxDynamicSharedMemorySize, SMEM2_TOTAL);

    // 1) text -> fp16, W -> fp16
    conv_inputs<<<2304, 256>>>(text, weight);
    // 2) adj -> fp16, row-normalized (rowsum fused)
    adj_convert<<<(B_ * R_ * N_) / 8, 256>>>(adj);
    // 3) Z = text @ W (fp16 1-pass HMMA)
    rgc_stage1<<<dim3(DOUT_ / 128, N_ / 128, B_ * R_), 256, SMEM1_TOTAL>>>();
    // 4) per-relation partials (256x128 tiles, ratio-4 warp tiles, grid 256)
    rgc_stage2<<<dim3(2 * R_, N_ / 256, B_), 256, SMEM2_TOTAL>>>(bias);
    // 5) out = sum of 4 partials
    reduce_out<<<(B_ * N_ * DOUT_) / 4 / 256, 256>>>(out);
}

// round 16
// speedup vs baseline: 1.1093x; 1.0689x over previous
#include <cuda_runtime.h>
#include <cuda_fp16.h>
#include <cstdint>

#define B_    8
#define R_    4
#define N_    1024
#define DIN_  256
#define DOUT_ 256

#define ADJ_SCALE 1024.0f
#define INV_SCALE (1.0f / 1024.0f)

// ---------------------------------------------------------------------------
// Global scratch (device globals; allocation in kernel_launch is forbidden)
// ---------------------------------------------------------------------------
__device__ __half g_text[(size_t)B_ * N_ * DIN_];
__device__ __half g_W[(size_t)R_ * DIN_ * DOUT_];
__device__ __half g_Z[(size_t)B_ * R_ * N_ * DOUT_];     // Z[b,r][j][d] fp16
__device__ __half g_adj[(size_t)B_ * R_ * N_ * N_];      // rinv*1024-scaled adj (fp16)
#define PART_HALF ((size_t)B_ * N_ * DOUT_)              // 2,097,152 floats
__device__ float  g_part[2 * PART_HALF];                 // K-split partials (16 MB)

// ---------------------------------------------------------------------------
// PTX helpers (compute_103-safe: mma.sync / ldmatrix / cp.async)
// ---------------------------------------------------------------------------
__device__ __forceinline__ uint32_t smem_u32(const void* p) {
    uint32_t a;
    asm("{ .reg .u64 t; cvta.to.shared.u64 t, %1; cvt.u32.u64 %0, t; }" : "=r"(a) : "l"(p));
    return a;
}
__device__ __forceinline__ void ldsm_x4(uint32_t addr, uint32_t& r0, uint32_t& r1,
                                        uint32_t& r2, uint32_t& r3) {
    asm volatile("ldmatrix.sync.aligned.m8n8.x4.shared.b16 {%0,%1,%2,%3}, [%4];"
                 : "=r"(r0), "=r"(r1), "=r"(r2), "=r"(r3) : "r"(addr));
}
__device__ __forceinline__ void ldsm_x4_t(uint32_t addr, uint32_t& r0, uint32_t& r1,
                                          uint32_t& r2, uint32_t& r3) {
    asm volatile("ldmatrix.sync.aligned.m8n8.x4.trans.shared.b16 {%0,%1,%2,%3}, [%4];"
                 : "=r"(r0), "=r"(r1), "=r"(r2), "=r"(r3) : "r"(addr));
}
__device__ __forceinline__ void mma_f16(float* c, const uint32_t a[4], uint32_t b0, uint32_t b1) {
    asm volatile("mma.sync.aligned.m16n8k16.row.col.f32.f16.f16.f32 "
                 "{%0,%1,%2,%3}, {%4,%5,%6,%7}, {%8,%9}, {%0,%1,%2,%3};"
                 : "+f"(c[0]), "+f"(c[1]), "+f"(c[2]), "+f"(c[3])
                 : "r"(a[0]), "r"(a[1]), "r"(a[2]), "r"(a[3]), "r"(b0), "r"(b1));
}
#define CP_ASYNC16(dst, src) \
    asm volatile("cp.async.cg.shared.global [%0], [%1], 16;" :: "r"(dst), "l"(src) : "memory")
#define CP_COMMIT()  asm volatile("cp.async.commit_group;" ::: "memory")
#define CP_WAIT0()   asm volatile("cp.async.wait_group 0;" ::: "memory")
#define CP_WAIT1()   asm volatile("cp.async.wait_group 1;" ::: "memory")

__device__ __forceinline__ uint32_t pack_h2(float x, float y) {
    __half hx = __float2half_rn(x), hy = __float2half_rn(y);
    return ((uint32_t)__half_as_ushort(hy) << 16) | __half_as_ushort(hx);
}

// ---------------------------------------------------------------------------
// smem layouts, padded strides — conflict-free ldmatrix
//   A-row: 64 fp16 = 128B, stride 144. B tile: 64 rows x 128 fp16, stride 272.
// ---------------------------------------------------------------------------
#define A_STRIDE  144
#define B_STRIDE  272
// stage 1 buffer: A (128 rows) + B
#define S1_OFF_A   0
#define S1_OFF_B   18432
#define S1_BUF     35840
#define SMEM1_TOTAL (2 * S1_BUF)           // 71680
// stage 2 buffer: A (128 rows) + B ; 3-stage pipeline, 2 CTAs/SM
#define S2_OFF_A   0
#define S2_OFF_B   18432
#define S2_BUF     35840
#define S2_STAGES  3
#define SMEM2_TOTAL (S2_STAGES * S2_BUF)   // 107520 -> 2 CTAs/SM

// 8 warps: warp (wm, wn) = (warp&3, warp>>2) computes 32x64 of the 128x128 tile.
// Single-pass fp16 chunk (shared by both stages; proven R9/R14 shape).
__device__ __forceinline__ void compute_chunk(uint32_t sb_buf, uint32_t offA, uint32_t offB,
                                              int wm, int wn, int g, int lr,
                                              float (&acc)[2][8][4]) {
#pragma unroll
    for (int ks = 0; ks < 4; ++ks) {
        const int k0 = ks * 16;
        uint32_t aa[2][4];
#pragma unroll
        for (int mf = 0; mf < 2; ++mf) {
            uint32_t row  = wm * 32 + mf * 16 + (g & 1) * 8 + lr;
            uint32_t colb = (uint32_t)((g >> 1) * 16 + k0 * 2);
            ldsm_x4(sb_buf + offA + row * A_STRIDE + colb,
                    aa[mf][0], aa[mf][1], aa[mf][2], aa[mf][3]);
        }
        uint32_t bb[8][2];
#pragma unroll
        for (int nb = 0; nb < 4; ++nb) {
            uint32_t krow = (uint32_t)(k0 + (g & 1) * 8 + lr);
            uint32_t colb = (uint32_t)((wn * 64 + nb * 16 + (g >> 1) * 8) * 2);
            uint32_t q0, q1, q2, q3;
            ldsm_x4_t(sb_buf + offB + krow * B_STRIDE + colb, q0, q1, q2, q3);
            bb[nb * 2][0] = q0; bb[nb * 2][1] = q1;
            bb[nb * 2 + 1][0] = q2; bb[nb * 2 + 1][1] = q3;
        }
#pragma unroll
        for (int mf = 0; mf < 2; ++mf)
#pragma unroll
            for (int nf = 0; nf < 8; ++nf)
                mma_f16(acc[mf][nf], aa[mf], bb[nf][0], bb[nf][1]);
    }
}

// ---------------------------------------------------------------------------
// conv_inputs: text -> fp16 ; W -> fp16.
// ---------------------------------------------------------------------------
__global__ __launch_bounds__(256) void conv_inputs(const float* __restrict__ text,
                                                   const float* __restrict__ weight) {
    const size_t NT4 = (size_t)B_ * N_ * DIN_ / 4;            // 524288 float4s
    size_t i = (size_t)blockIdx.x * 256 + threadIdx.x;        // total 589824
    if (i < NT4) {
        float4 v = reinterpret_cast<const float4*>(text)[i];
        *reinterpret_cast<uint2*>(g_text + i * 4) =
            make_uint2(pack_h2(v.x, v.y), pack_h2(v.z, v.w));
    } else {
        size_t j = i - NT4;
        float4 v = reinterpret_cast<const float4*>(weight)[j];
        *reinterpret_cast<uint2*>(g_W + j * 4) =
            make_uint2(pack_h2(v.x, v.y), pack_h2(v.z, v.w));
    }
}

// ---------------------------------------------------------------------------
// adj_convert: one warp per row. rowsum -> rinv; write (adj * rinv * 1024) as
// fp16. Standalone (fusing with smem-heavy launches regresses; R11).
// ---------------------------------------------------------------------------
__global__ __launch_bounds__(256) void adj_convert(const float* __restrict__ adj) {
    const int warp = threadIdx.x >> 5, lane = threadIdx.x & 31;
    const int row  = blockIdx.x * 8 + warp;                    // 0 .. 32767
    const float* p = adj + (size_t)row * N_;

    float4 v[8];
    float s = 0.f;
#pragma unroll
    for (int t = 0; t < 8; ++t) {
        v[t] = *reinterpret_cast<const float4*>(p + t * 128 + lane * 4);
        s += (v[t].x + v[t].y) + (v[t].z + v[t].w);
    }
#pragma unroll
    for (int o = 16; o > 0; o >>= 1) s += __shfl_xor_sync(0xffffffffu, s, o);
    const float rinv = (s == 0.f) ? 0.f : ADJ_SCALE / s;

    __half* hp = g_adj + (size_t)row * N_;
#pragma unroll
    for (int t = 0; t < 8; ++t) {
        *reinterpret_cast<uint2*>(hp + t * 128 + lane * 4) =
            make_uint2(pack_h2(v[t].x * rinv, v[t].y * rinv),
                       pack_h2(v[t].z * rinv, v[t].w * rinv));
    }
}

// ---------------------------------------------------------------------------
// Stage 1: Z[b,r] = text[b] @ W[r]  (fp16 1-pass HMMA); writes Z fp16.
// ---------------------------------------------------------------------------
__global__ __launch_bounds__(256, 1) void rgc_stage1() {
    extern __shared__ char smem[];
    const uint32_t sb = smem_u32(smem);
    const int tid = threadIdx.x, lane = tid & 31, warp = tid >> 5;
    const int wm = warp & 3, wn = warp >> 2;
    const int g = lane >> 3, lr = lane & 7;

    const int bz = blockIdx.z;            // b*R + r
    const int b  = bz >> 2, r = bz & 3;
    const int tile_m = blockIdx.y * 128;  // j
    const int tile_n = blockIdx.x * 128;  // d

    float acc[2][8][4];
#pragma unroll
    for (int mf = 0; mf < 2; ++mf)
#pragma unroll
        for (int nf = 0; nf < 8; ++nf)
#pragma unroll
            for (int q = 0; q < 4; ++q) acc[mf][nf][q] = 0.f;

    auto issue = [&](int kc) {
        const uint32_t bufb = (uint32_t)(kc & 1) * S1_BUF;
        const __half* tp = g_text + ((size_t)b * N_ + tile_m) * DIN_ + kc * 64;
#pragma unroll
        for (int i = 0; i < 4; ++i) {
            int idx = i * 256 + tid;
            int row = idx >> 3, k8 = idx & 7;
            CP_ASYNC16(sb + bufb + row * A_STRIDE + k8 * 16 + S1_OFF_A,
                       tp + (size_t)row * DIN_ + k8 * 8);
        }
        const __half* wp = g_W + ((size_t)r * DIN_ + kc * 64) * DOUT_ + tile_n;
#pragma unroll
        for (int i = 0; i < 4; ++i) {
            int idx = i * 256 + tid;
            int k = idx >> 4, n16 = idx & 15;
            CP_ASYNC16(sb + bufb + k * B_STRIDE + n16 * 16 + S1_OFF_B,
                       wp + (size_t)k * DOUT_ + n16 * 8);
        }
        CP_COMMIT();
    };

    issue(0);
    CP_WAIT0();
    __syncthreads();

    for (int c = 0; c < 4; ++c) {
        if (c + 1 < 4) issue(c + 1);
        compute_chunk(sb + (uint32_t)(c & 1) * S1_BUF, S1_OFF_A, S1_OFF_B, wm, wn, g, lr, acc);
        CP_WAIT0();
        __syncthreads();
    }

    // Epilogue: Z fp16
#pragma unroll
    for (int mf = 0; mf < 2; ++mf)
#pragma unroll
        for (int nf = 0; nf < 8; ++nf) {
            int row0 = tile_m + wm * 32 + mf * 16 + (lane >> 2);
            int col  = tile_n + wn * 64 + nf * 8 + (lane & 3) * 2;
            size_t off0 = ((size_t)bz * N_ + row0) * DOUT_ + col;
            *reinterpret_cast<uint32_t*>(&g_Z[off0]) = pack_h2(acc[mf][nf][0], acc[mf][nf][1]);
            size_t off1 = off0 + (size_t)8 * DOUT_;
            *reinterpret_cast<uint32_t*>(&g_Z[off1]) = pack_h2(acc[mf][nf][2], acc[mf][nf][3]);
        }
}

// ---------------------------------------------------------------------------
// Stage 2 (R14-proven): g_part[half] = partial over relations {2*half, 2*half+1}
// (half 0 folds bias). 128x128 CTA tile, warp tile 32x64, 3-stage pipeline,
// grid 256 -> genuine 2 CTAs/SM (two independent barrier domains).
// ---------------------------------------------------------------------------
__global__ __launch_bounds__(256, 2) void rgc_stage2(const float* __restrict__ bias) {
    extern __shared__ char smem[];
    const uint32_t sb = smem_u32(smem);
    const int tid = threadIdx.x, lane = tid & 31, warp = tid >> 5;
    const int wm = warp & 3, wn = warp >> 2;
    const int g = lane >> 3, lr = lane & 7;

    const int half   = blockIdx.x >> 1;
    const int b      = blockIdx.z;
    const int tile_m = blockIdx.y * 128;           // i
    const int tile_n = (blockIdx.x & 1) * 128;     // d

    float acc[2][8][4];
#pragma unroll
    for (int mf = 0; mf < 2; ++mf)
#pragma unroll
        for (int nf = 0; nf < 8; ++nf)
#pragma unroll
            for (int q = 0; q < 4; ++q) acc[mf][nf][q] = 0.f;

    // chunk c in [half*32, half*32+32): r = c>>4, kc = c&15
    auto issue = [&](int c) {
        const int r = c >> 4, kc = c & 15;
        const uint32_t bufb = (uint32_t)(c % S2_STAGES) * S2_BUF;
        const __half* ap = g_adj + (((size_t)(b * R_ + r)) * N_ + tile_m) * N_ + kc * 64;
#pragma unroll
        for (int i = 0; i < 4; ++i) {
            int idx = i * 256 + tid;
            int row = idx >> 3, k8 = idx & 7;
            CP_ASYNC16(sb + bufb + row * A_STRIDE + k8 * 16 + S2_OFF_A,
                       ap + (size_t)row * N_ + k8 * 8);
        }
        const __half* zp = g_Z + (((size_t)(b * R_ + r)) * N_ + kc * 64) * DOUT_ + tile_n;
#pragma unroll
        for (int i = 0; i < 4; ++i) {
            int idx = i * 256 + tid;
            int k = idx >> 4, n16 = idx & 15;
            CP_ASYNC16(sb + bufb + k * B_STRIDE + n16 * 16 + S2_OFF_B,
                       zp + (size_t)k * DOUT_ + n16 * 8);
        }
        CP_COMMIT();
    };

    const int c0 = half * 32, c1 = c0 + 32;
    issue(c0); issue(c0 + 1);

    for (int c = c0; c < c1; ++c) {
        CP_WAIT1();                      // chunk c landed (1 younger may be in flight)
        __syncthreads();                 // all warps past compute(c-1); its buffer free
        if (c + 2 < c1) issue(c + 2); else CP_COMMIT();   // uniform group accounting
        compute_chunk(sb + (uint32_t)(c % S2_STAGES) * S2_BUF, S2_OFF_A, S2_OFF_B,
                      wm, wn, g, lr, acc);
    }

    // Epilogue: undo ADJ_SCALE; half 0 folds bias; store partial fp32
    float* po = g_part + (size_t)half * PART_HALF + ((size_t)b * N_) * DOUT_;
#pragma unroll
    for (int mf = 0; mf < 2; ++mf)
#pragma unroll
        for (int nf = 0; nf < 8; ++nf) {
            int row0 = tile_m + wm * 32 + mf * 16 + (lane >> 2);
            int col  = tile_n + wn * 64 + nf * 8 + (lane & 3) * 2;
            float b0 = (half == 0) ? bias[col] : 0.f;
            float b1 = (half == 0) ? bias[col + 1] : 0.f;
            float* o0 = po + (size_t)row0 * DOUT_ + col;
            *reinterpret_cast<float2*>(o0) =
                make_float2(acc[mf][nf][0] * INV_SCALE + b0, acc[mf][nf][1] * INV_SCALE + b1);
            float* o1 = o0 + (size_t)8 * DOUT_;
            *reinterpret_cast<float2*>(o1) =
                make_float2(acc[mf][nf][2] * INV_SCALE + b0, acc[mf][nf][3] * INV_SCALE + b1);
        }
}

// ---------------------------------------------------------------------------
// reduce_out: out = part0 + part1 (float4 streaming, 24 MB traffic).
// ---------------------------------------------------------------------------
__global__ __launch_bounds__(256) void reduce_out(float* __restrict__ out) {
    size_t i = ((size_t)blockIdx.x * 256 + threadIdx.x);      // float4 index, 524288 total
    float4 a = reinterpret_cast<const float4*>(g_part)[i];
    float4 c = reinterpret_cast<const float4*>(g_part + PART_HALF)[i];
    reinterpret_cast<float4*>(out)[i] =
        make_float4(a.x + c.x, a.y + c.y, a.z + c.z, a.w + c.w);
}

// ---------------------------------------------------------------------------
extern "C" void kernel_launch(void* const* d_in, const int* in_sizes, int n_in,
                              void* d_out, int out_size) {
    const float* text   = (const float*)d_in[0];  // [8,1024,256]
    const float* adj    = (const float*)d_in[1];  // [8,4,1024,1024]
    const float* weight = (const float*)d_in[2];  // [4,256,256]
    const float* bias   = (const float*)d_in[3];  // [256]
    float* out = (float*)d_out;                   // [8,1024,256]

    cudaFuncSetAttribute(rgc_stage1, cudaFuncAttributeMaxDynamicSharedMemorySize, SMEM1_TOTAL);
    cudaFuncSetAttribute(rgc_stage2, cudaFuncAttributeMaxDynamicSharedMemorySize, SMEM2_TOTAL);

    // 1) text -> fp16, W -> fp16
    conv_inputs<<<2304, 256>>>(text, weight);
    // 2) adj -> fp16, row-normalized (rowsum fused)
    adj_convert<<<(B_ * R_ * N_) / 8, 256>>>(adj);
    // 3) Z = text @ W (fp16 1-pass HMMA)
    rgc_stage1<<<dim3(DOUT_ / 128, N_ / 128, B_ * R_), 256, SMEM1_TOTAL>>>();
    // 4) partials over relation halves (grid 256 -> true 2 CTAs/SM)
    rgc_stage2<<<dim3(2 * (DOUT_ / 128), N_ / 128, B_), 256, SMEM2_TOTAL>>>(bias);
    // 5) out = part0 + part1
    reduce_out<<<(B_ * N_ * DOUT_) / 4 / 256, 256>>>(out);
}

// round 17
// speedup vs baseline: 1.1438x; 1.0311x over previous
#include <cuda_runtime.h>
#include <cuda_fp16.h>
#include <cstdint>

#define B_    8
#define R_    4
#define N_    1024
#define DIN_  256
#define DOUT_ 256

#define ADJ_SCALE 1024.0f
#define INV_SCALE (1.0f / 1024.0f)

// ---------------------------------------------------------------------------
// Global scratch (device globals; allocation in kernel_launch is forbidden)
// ---------------------------------------------------------------------------
__device__ __half g_text[(size_t)B_ * N_ * DIN_];
__device__ __half g_W[(size_t)R_ * DIN_ * DOUT_];
__device__ __half g_Z[(size_t)B_ * R_ * N_ * DOUT_];     // Z[b,r][j][d] fp16
__device__ __half g_adj[(size_t)B_ * R_ * N_ * N_];      // rinv*1024-scaled adj (fp16)
#define PART_HALF ((size_t)B_ * N_ * DOUT_)              // 2,097,152 floats
__device__ float  g_part[2 * PART_HALF];                 // K-split partials (16 MB)

// ---------------------------------------------------------------------------
// PTX helpers (compute_103-safe: mma.sync / ldmatrix / cp.async)
// ---------------------------------------------------------------------------
__device__ __forceinline__ uint32_t smem_u32(const void* p) {
    uint32_t a;
    asm("{ .reg .u64 t; cvta.to.shared.u64 t, %1; cvt.u32.u64 %0, t; }" : "=r"(a) : "l"(p));
    return a;
}
__device__ __forceinline__ void ldsm_x4(uint32_t addr, uint32_t& r0, uint32_t& r1,
                                        uint32_t& r2, uint32_t& r3) {
    asm volatile("ldmatrix.sync.aligned.m8n8.x4.shared.b16 {%0,%1,%2,%3}, [%4];"
                 : "=r"(r0), "=r"(r1), "=r"(r2), "=r"(r3) : "r"(addr));
}
__device__ __forceinline__ void ldsm_x4_t(uint32_t addr, uint32_t& r0, uint32_t& r1,
                                          uint32_t& r2, uint32_t& r3) {
    asm volatile("ldmatrix.sync.aligned.m8n8.x4.trans.shared.b16 {%0,%1,%2,%3}, [%4];"
                 : "=r"(r0), "=r"(r1), "=r"(r2), "=r"(r3) : "r"(addr));
}
__device__ __forceinline__ void mma_f16(float* c, const uint32_t a[4], uint32_t b0, uint32_t b1) {
    asm volatile("mma.sync.aligned.m16n8k16.row.col.f32.f16.f16.f32 "
                 "{%0,%1,%2,%3}, {%4,%5,%6,%7}, {%8,%9}, {%0,%1,%2,%3};"
                 : "+f"(c[0]), "+f"(c[1]), "+f"(c[2]), "+f"(c[3])
                 : "r"(a[0]), "r"(a[1]), "r"(a[2]), "r"(a[3]), "r"(b0), "r"(b1));
}
#define CP_ASYNC16(dst, src) \
    asm volatile("cp.async.cg.shared.global [%0], [%1], 16;" :: "r"(dst), "l"(src) : "memory")
#define CP_COMMIT()  asm volatile("cp.async.commit_group;" ::: "memory")
#define CP_WAIT0()   asm volatile("cp.async.wait_group 0;" ::: "memory")
#define CP_WAIT1()   asm volatile("cp.async.wait_group 1;" ::: "memory")

__device__ __forceinline__ uint32_t pack_h2(float x, float y) {
    __half hx = __float2half_rn(x), hy = __float2half_rn(y);
    return ((uint32_t)__half_as_ushort(hy) << 16) | __half_as_ushort(hx);
}

// ---------------------------------------------------------------------------
// smem layouts, padded strides — conflict-free ldmatrix
//   A-row: 64 fp16 = 128B, stride 144. B tile: 64 rows x 128 fp16, stride 272.
// ---------------------------------------------------------------------------
#define A_STRIDE  144
#define B_STRIDE  272
// stage 1 buffer: A (128 rows) + B
#define S1_OFF_A   0
#define S1_OFF_B   18432
#define S1_BUF     35840
#define SMEM1_TOTAL (2 * S1_BUF)           // 71680
// stage 2 buffer: A (128 rows) + B ; 3-stage pipeline, 2 CTAs/SM
#define S2_OFF_A   0
#define S2_OFF_B   18432
#define S2_BUF     35840
#define S2_STAGES  3
#define SMEM2_TOTAL (S2_STAGES * S2_BUF)   // 107520 -> 2 CTAs/SM

// 8 warps: warp (wm, wn) = (warp&3, warp>>2) computes 32x64 of the 128x128 tile.
// Single-pass fp16 chunk (proven R9/R14 shape).
__device__ __forceinline__ void compute_chunk(uint32_t sb_buf, uint32_t offA, uint32_t offB,
                                              int wm, int wn, int g, int lr,
                                              float (&acc)[2][8][4]) {
#pragma unroll
    for (int ks = 0; ks < 4; ++ks) {
        const int k0 = ks * 16;
        uint32_t aa[2][4];
#pragma unroll
        for (int mf = 0; mf < 2; ++mf) {
            uint32_t row  = wm * 32 + mf * 16 + (g & 1) * 8 + lr;
            uint32_t colb = (uint32_t)((g >> 1) * 16 + k0 * 2);
            ldsm_x4(sb_buf + offA + row * A_STRIDE + colb,
                    aa[mf][0], aa[mf][1], aa[mf][2], aa[mf][3]);
        }
        uint32_t bb[8][2];
#pragma unroll
        for (int nb = 0; nb < 4; ++nb) {
            uint32_t krow = (uint32_t)(k0 + (g & 1) * 8 + lr);
            uint32_t colb = (uint32_t)((wn * 64 + nb * 16 + (g >> 1) * 8) * 2);
            uint32_t q0, q1, q2, q3;
            ldsm_x4_t(sb_buf + offB + krow * B_STRIDE + colb, q0, q1, q2, q3);
            bb[nb * 2][0] = q0; bb[nb * 2][1] = q1;
            bb[nb * 2 + 1][0] = q2; bb[nb * 2 + 1][1] = q3;
        }
#pragma unroll
        for (int mf = 0; mf < 2; ++mf)
#pragma unroll
            for (int nf = 0; nf < 8; ++nf)
                mma_f16(acc[mf][nf], aa[mf], bb[nf][0], bb[nf][1]);
    }
}

// ---------------------------------------------------------------------------
// conv_inputs: text -> fp16 ; W -> fp16.
// ---------------------------------------------------------------------------
__global__ __launch_bounds__(256) void conv_inputs(const float* __restrict__ text,
                                                   const float* __restrict__ weight) {
    const size_t NT4 = (size_t)B_ * N_ * DIN_ / 4;            // 524288 float4s
    size_t i = (size_t)blockIdx.x * 256 + threadIdx.x;        // total 589824
    if (i < NT4) {
        float4 v = reinterpret_cast<const float4*>(text)[i];
        *reinterpret_cast<uint2*>(g_text + i * 4) =
            make_uint2(pack_h2(v.x, v.y), pack_h2(v.z, v.w));
    } else {
        size_t j = i - NT4;
        float4 v = reinterpret_cast<const float4*>(weight)[j];
        *reinterpret_cast<uint2*>(g_W + j * 4) =
            make_uint2(pack_h2(v.x, v.y), pack_h2(v.z, v.w));
    }
}

// ---------------------------------------------------------------------------
// adj_convert: one warp per row. rowsum -> rinv; write (adj * rinv * 1024) as
// fp16. Standalone launch (own occupancy); runs CONCURRENTLY with
// conv_inputs/stage1 via a forked stream in the captured graph.
// ---------------------------------------------------------------------------
__global__ __launch_bounds__(256) void adj_convert(const float* __restrict__ adj) {
    const int warp = threadIdx.x >> 5, lane = threadIdx.x & 31;
    const int row  = blockIdx.x * 8 + warp;                    // 0 .. 32767
    const float* p = adj + (size_t)row * N_;

    float4 v[8];
    float s = 0.f;
#pragma unroll
    for (int t = 0; t < 8; ++t) {
        v[t] = *reinterpret_cast<const float4*>(p + t * 128 + lane * 4);
        s += (v[t].x + v[t].y) + (v[t].z + v[t].w);
    }
#pragma unroll
    for (int o = 16; o > 0; o >>= 1) s += __shfl_xor_sync(0xffffffffu, s, o);
    const float rinv = (s == 0.f) ? 0.f : ADJ_SCALE / s;

    __half* hp = g_adj + (size_t)row * N_;
#pragma unroll
    for (int t = 0; t < 8; ++t) {
        *reinterpret_cast<uint2*>(hp + t * 128 + lane * 4) =
            make_uint2(pack_h2(v[t].x * rinv, v[t].y * rinv),
                       pack_h2(v[t].z * rinv, v[t].w * rinv));
    }
}

// ---------------------------------------------------------------------------
// Stage 1: Z[b,r] = text[b] @ W[r]  (fp16 1-pass HMMA); writes Z fp16.
// ---------------------------------------------------------------------------
__global__ __launch_bounds__(256, 1) void rgc_stage1() {
    extern __shared__ char smem[];
    const uint32_t sb = smem_u32(smem);
    const int tid = threadIdx.x, lane = tid & 31, warp = tid >> 5;
    const int wm = warp & 3, wn = warp >> 2;
    const int g = lane >> 3, lr = lane & 7;

    const int bz = blockIdx.z;            // b*R + r
    const int b  = bz >> 2, r = bz & 3;
    const int tile_m = blockIdx.y * 128;  // j
    const int tile_n = blockIdx.x * 128;  // d

    float acc[2][8][4];
#pragma unroll
    for (int mf = 0; mf < 2; ++mf)
#pragma unroll
        for (int nf = 0; nf < 8; ++nf)
#pragma unroll
            for (int q = 0; q < 4; ++q) acc[mf][nf][q] = 0.f;

    auto issue = [&](int kc) {
        const uint32_t bufb = (uint32_t)(kc & 1) * S1_BUF;
        const __half* tp = g_text + ((size_t)b * N_ + tile_m) * DIN_ + kc * 64;
#pragma unroll
        for (int i = 0; i < 4; ++i) {
            int idx = i * 256 + tid;
            int row = idx >> 3, k8 = idx & 7;
            CP_ASYNC16(sb + bufb + row * A_STRIDE + k8 * 16 + S1_OFF_A,
                       tp + (size_t)row * DIN_ + k8 * 8);
        }
        const __half* wp = g_W + ((size_t)r * DIN_ + kc * 64) * DOUT_ + tile_n;
#pragma unroll
        for (int i = 0; i < 4; ++i) {
            int idx = i * 256 + tid;
            int k = idx >> 4, n16 = idx & 15;
            CP_ASYNC16(sb + bufb + k * B_STRIDE + n16 * 16 + S1_OFF_B,
                       wp + (size_t)k * DOUT_ + n16 * 8);
        }
        CP_COMMIT();
    };

    issue(0);
    CP_WAIT0();
    __syncthreads();

    for (int c = 0; c < 4; ++c) {
        if (c + 1 < 4) issue(c + 1);
        compute_chunk(sb + (uint32_t)(c & 1) * S1_BUF, S1_OFF_A, S1_OFF_B, wm, wn, g, lr, acc);
        CP_WAIT0();
        __syncthreads();
    }

    // Epilogue: Z fp16
#pragma unroll
    for (int mf = 0; mf < 2; ++mf)
#pragma unroll
        for (int nf = 0; nf < 8; ++nf) {
            int row0 = tile_m + wm * 32 + mf * 16 + (lane >> 2);
            int col  = tile_n + wn * 64 + nf * 8 + (lane & 3) * 2;
            size_t off0 = ((size_t)bz * N_ + row0) * DOUT_ + col;
            *reinterpret_cast<uint32_t*>(&g_Z[off0]) = pack_h2(acc[mf][nf][0], acc[mf][nf][1]);
            size_t off1 = off0 + (size_t)8 * DOUT_;
            *reinterpret_cast<uint32_t*>(&g_Z[off1]) = pack_h2(acc[mf][nf][2], acc[mf][nf][3]);
        }
}

// ---------------------------------------------------------------------------
// Stage 2: g_part[half] = partial over relations {2*half, 2*half+1}
// (half 0 folds bias). 128x128 CTA tile, warp tile 32x64, 3-stage pipeline,
// grid 256 -> genuine 2 CTAs/SM.
// ---------------------------------------------------------------------------
__global__ __launch_bounds__(256, 2) void rgc_stage2(const float* __restrict__ bias) {
    extern __shared__ char smem[];
    const uint32_t sb = smem_u32(smem);
    const int tid = threadIdx.x, lane = tid & 31, warp = tid >> 5;
    const int wm = warp & 3, wn = warp >> 2;
    const int g = lane >> 3, lr = lane & 7;

    const int half   = blockIdx.x >> 1;
    const int b      = blockIdx.z;
    const int tile_m = blockIdx.y * 128;           // i
    const int tile_n = (blockIdx.x & 1) * 128;     // d

    float acc[2][8][4];
#pragma unroll
    for (int mf = 0; mf < 2; ++mf)
#pragma unroll
        for (int nf = 0; nf < 8; ++nf)
#pragma unroll
            for (int q = 0; q < 4; ++q) acc[mf][nf][q] = 0.f;

    // chunk c in [half*32, half*32+32): r = c>>4, kc = c&15
    auto issue = [&](int c) {
        const int r = c >> 4, kc = c & 15;
        const uint32_t bufb = (uint32_t)(c % S2_STAGES) * S2_BUF;
        const __half* ap = g_adj + (((size_t)(b * R_ + r)) * N_ + tile_m) * N_ + kc * 64;
#pragma unroll
        for (int i = 0; i < 4; ++i) {
            int idx = i * 256 + tid;
            int row = idx >> 3, k8 = idx & 7;
            CP_ASYNC16(sb + bufb + row * A_STRIDE + k8 * 16 + S2_OFF_A,
                       ap + (size_t)row * N_ + k8 * 8);
        }
        const __half* zp = g_Z + (((size_t)(b * R_ + r)) * N_ + kc * 64) * DOUT_ + tile_n;
#pragma unroll
        for (int i = 0; i < 4; ++i) {
            int idx = i * 256 + tid;
            int k = idx >> 4, n16 = idx & 15;
            CP_ASYNC16(sb + bufb + k * B_STRIDE + n16 * 16 + S2_OFF_B,
                       zp + (size_t)k * DOUT_ + n16 * 8);
        }
        CP_COMMIT();
    };

    const int c0 = half * 32, c1 = c0 + 32;
    issue(c0); issue(c0 + 1);

    for (int c = c0; c < c1; ++c) {
        CP_WAIT1();                      // chunk c landed (1 younger may be in flight)
        __syncthreads();                 // all warps past compute(c-1); its buffer free
        if (c + 2 < c1) issue(c + 2); else CP_COMMIT();   // uniform group accounting
        compute_chunk(sb + (uint32_t)(c % S2_STAGES) * S2_BUF, S2_OFF_A, S2_OFF_B,
                      wm, wn, g, lr, acc);
    }

    // Epilogue: undo ADJ_SCALE; half 0 folds bias; store partial fp32
    float* po = g_part + (size_t)half * PART_HALF + ((size_t)b * N_) * DOUT_;
#pragma unroll
    for (int mf = 0; mf < 2; ++mf)
#pragma unroll
        for (int nf = 0; nf < 8; ++nf) {
            int row0 = tile_m + wm * 32 + mf * 16 + (lane >> 2);
            int col  = tile_n + wn * 64 + nf * 8 + (lane & 3) * 2;
            float b0 = (half == 0) ? bias[col] : 0.f;
            float b1 = (half == 0) ? bias[col + 1] : 0.f;
            float* o0 = po + (size_t)row0 * DOUT_ + col;
            *reinterpret_cast<float2*>(o0) =
                make_float2(acc[mf][nf][0] * INV_SCALE + b0, acc[mf][nf][1] * INV_SCALE + b1);
            float* o1 = o0 + (size_t)8 * DOUT_;
            *reinterpret_cast<float2*>(o1) =
                make_float2(acc[mf][nf][2] * INV_SCALE + b0, acc[mf][nf][3] * INV_SCALE + b1);
        }
}

// ---------------------------------------------------------------------------
// reduce_out: out = part0 + part1 (float4 streaming, 24 MB traffic).
// ---------------------------------------------------------------------------
__global__ __launch_bounds__(256) void reduce_out(float* __restrict__ out) {
    size_t i = ((size_t)blockIdx.x * 256 + threadIdx.x);      // float4 index, 524288 total
    float4 a = reinterpret_cast<const float4*>(g_part)[i];
    float4 c = reinterpret_cast<const float4*>(g_part + PART_HALF)[i];
    reinterpret_cast<float4*>(out)[i] =
        make_float4(a.x + c.x, a.y + c.y, a.z + c.z, a.w + c.w);
}

// ---------------------------------------------------------------------------
// Graph-parallel schedule:
//   branch A (capture stream): conv_inputs -> rgc_stage1
//   branch B (forked stream):  adj_convert        (independent of branch A)
//   join -> rgc_stage2 -> reduce_out
// Streams/events are created per call (host-side only; no device allocation)
// and destroyed at the end; the captured graph retains the parallel branches.
// ---------------------------------------------------------------------------
extern "C" void kernel_launch(void* const* d_in, const int* in_sizes, int n_in,
                              void* d_out, int out_size) {
    const float* text   = (const float*)d_in[0];  // [8,1024,256]
    const float* adj    = (const float*)d_in[1];  // [8,4,1024,1024]
    const float* weight = (const float*)d_in[2];  // [4,256,256]
    const float* bias   = (const float*)d_in[3];  // [256]
    float* out = (float*)d_out;                   // [8,1024,256]

    cudaFuncSetAttribute(rgc_stage1, cudaFuncAttributeMaxDynamicSharedMemorySize, SMEM1_TOTAL);
    cudaFuncSetAttribute(rgc_stage2, cudaFuncAttributeMaxDynamicSharedMemorySize, SMEM2_TOTAL);

    cudaStream_t sB;
    cudaStreamCreateWithFlags(&sB, cudaStreamNonBlocking);
    cudaEvent_t evFork, evAdj;
    cudaEventCreateWithFlags(&evFork, cudaEventDisableTiming);
    cudaEventCreateWithFlags(&evAdj, cudaEventDisableTiming);

    // Fork: branch B waits on the capture stream's current front.
    cudaEventRecord(evFork, 0);
    cudaStreamWaitEvent(sB, evFork, 0);

    // Branch B: adj -> fp16, row-normalized (DRAM-bound).
    adj_convert<<<(B_ * R_ * N_) / 8, 256, 0, sB>>>(adj);
    cudaEventRecord(evAdj, sB);

    // Branch A: text/W -> fp16, then Z = text @ W (tensor-bound).
    conv_inputs<<<2304, 256>>>(text, weight);
    rgc_stage1<<<dim3(DOUT_ / 128, N_ / 128, B_ * R_), 256, SMEM1_TOTAL>>>();

    // Join: stage2 needs both g_adj (branch B) and g_Z (branch A).
    cudaStreamWaitEvent(0, evAdj, 0);
    rgc_stage2<<<dim3(2 * (DOUT_ / 128), N_ / 128, B_), 256, SMEM2_TOTAL>>>(bias);
    reduce_out<<<(B_ * N_ * DOUT_) / 4 / 256, 256>>>(out);

    cudaEventDestroy(evFork);
    cudaEventDestroy(evAdj);
    cudaStreamDestroy(sB);
}